// round 1
// baseline (speedup 1.0000x reference)
#include <cuda_runtime.h>
#include <math.h>

// Problem constants
constexpr int B_  = 2;
constexpr int L_  = 2048;
constexpr int D_  = 1024;
constexpr int NH  = 16;
constexpr int HD  = 64;
constexpr int M_  = B_ * L_;     // 4096 rows for projections

// Scratch (device globals; no allocation allowed)
__device__ float  g_Qp[B_ * NH * L_ * HD];   // (b, n, l, h) roped
__device__ float  g_Kp[B_ * NH * L_ * HD];   // (b, n, l, h) roped
__device__ float  g_Vp[B_ * NH * L_ * HD];   // (b, n, l, h)
__device__ float  g_Ctx[B_ * L_ * D_];       // attention output (b, l, d)
__device__ float2 g_rope[L_ * (HD / 2)];     // (cos, sin) per (l, i)

// ---------------------------------------------------------------------------
// RoPE table: g_rope[l*32 + i] = (cos(l*invfreq_i), sin(l*invfreq_i))
// invfreq_i = 10000^(-(2i)/64)
// ---------------------------------------------------------------------------
__global__ void rope_table_kernel() {
    int idx = blockIdx.x * blockDim.x + threadIdx.x;
    if (idx >= L_ * (HD / 2)) return;
    int l = idx >> 5;
    int i = idx & 31;
    float inv = powf(10000.0f, -(float)(2 * i) / 64.0f);
    float ang = (float)l * inv;
    float s, c;
    sincosf(ang, &s, &c);
    g_rope[idx] = make_float2(c, s);
}

// ---------------------------------------------------------------------------
// SGEMM: Y = X @ W^T + b.  X: [M_, D_], W: [D_, D_] (out, in) row-major.
// BM=BN=128, BK=16, 256 threads, 8x8 micro-tile per thread.
//
// gemm_qkv: grid (8, 32, 3); z picks q/k/v; epilogue applies RoPE (z<2) and
//           scatters to (b, n, l, h) layout.
// gemm_out: grid (8, 32); plain row-major write to output.
// ---------------------------------------------------------------------------
#define GBM 128
#define GBN 128
#define GBK 16

struct GemmAcc {
    float acc[8][8];
};

__device__ __forceinline__ void gemm_core(
    const float* __restrict__ X, const float* __restrict__ W,
    float (&Xs)[GBM][GBK + 1], float (&Ws)[GBN][GBK + 1],
    GemmAcc& A)
{
    int tid = threadIdx.x;
    int tx = tid & 15, ty = tid >> 4;
    int m0 = blockIdx.y * GBM;
    int n0 = blockIdx.x * GBN;

    #pragma unroll
    for (int i = 0; i < 8; i++)
        #pragma unroll
        for (int j = 0; j < 8; j++)
            A.acc[i][j] = 0.0f;

    int lr = tid >> 1;           // 0..127
    int lc = (tid & 1) * 8;      // 0 or 8

    for (int k0 = 0; k0 < D_; k0 += GBK) {
        // load X tile and W tile (each 128x16), 8 floats per thread per tile
        const float4* xp = (const float4*)(X + (size_t)(m0 + lr) * D_ + k0 + lc);
        const float4* wp = (const float4*)(W + (size_t)(n0 + lr) * D_ + k0 + lc);
        float4 xa = xp[0], xb = xp[1];
        float4 wa = wp[0], wb = wp[1];
        Xs[lr][lc + 0] = xa.x; Xs[lr][lc + 1] = xa.y; Xs[lr][lc + 2] = xa.z; Xs[lr][lc + 3] = xa.w;
        Xs[lr][lc + 4] = xb.x; Xs[lr][lc + 5] = xb.y; Xs[lr][lc + 6] = xb.z; Xs[lr][lc + 7] = xb.w;
        Ws[lr][lc + 0] = wa.x; Ws[lr][lc + 1] = wa.y; Ws[lr][lc + 2] = wa.z; Ws[lr][lc + 3] = wa.w;
        Ws[lr][lc + 4] = wb.x; Ws[lr][lc + 5] = wb.y; Ws[lr][lc + 6] = wb.z; Ws[lr][lc + 7] = wb.w;
        __syncthreads();

        #pragma unroll
        for (int kk = 0; kk < GBK; kk++) {
            float a[8], bb[8];
            #pragma unroll
            for (int i = 0; i < 8; i++) a[i] = Xs[ty + 16 * i][kk];
            #pragma unroll
            for (int j = 0; j < 8; j++) bb[j] = Ws[tx + 16 * j][kk];
            #pragma unroll
            for (int i = 0; i < 8; i++)
                #pragma unroll
                for (int j = 0; j < 8; j++)
                    A.acc[i][j] += a[i] * bb[j];
        }
        __syncthreads();
    }
}

__global__ __launch_bounds__(256) void gemm_qkv_kernel(
    const float* __restrict__ q, const float* __restrict__ k, const float* __restrict__ v,
    const float* __restrict__ Wq, const float* __restrict__ bq,
    const float* __restrict__ Wk, const float* __restrict__ bk,
    const float* __restrict__ Wv, const float* __restrict__ bv)
{
    __shared__ float Xs[GBM][GBK + 1];
    __shared__ float Ws[GBN][GBK + 1];

    int z = blockIdx.z;
    const float* X    = (z == 0) ? q  : (z == 1) ? k  : v;
    const float* W    = (z == 0) ? Wq : (z == 1) ? Wk : Wv;
    const float* bias = (z == 0) ? bq : (z == 1) ? bk : bv;
    float* dst        = (z == 0) ? g_Qp : (z == 1) ? g_Kp : g_Vp;

    GemmAcc A;
    gemm_core(X, W, Xs, Ws, A);

    int tid = threadIdx.x;
    int tx = tid & 15, ty = tid >> 4;
    int m0 = blockIdx.y * GBM;
    int n0 = blockIdx.x * GBN;

    float bj[8];
    #pragma unroll
    for (int j = 0; j < 8; j++) bj[j] = bias[n0 + tx + 16 * j];

    bool do_rope = (z < 2);

    #pragma unroll
    for (int i = 0; i < 8; i++) {
        int m = m0 + ty + 16 * i;
        int l = m & (L_ - 1);
        int bb = m >> 11;               // m / L_
        #pragma unroll
        for (int j = 0; j < 8; j++) {
            int o = n0 + tx + 16 * j;
            float val = A.acc[i][j] + bj[j];
            // pair exchange for RoPE: partner col = o^1 lives in adjacent lane
            float partner = __shfl_xor_sync(0xffffffffu, val, 1);
            if (do_rope) {
                int h = o & 63;
                float2 cs = g_rope[(l << 5) + (h >> 1)];
                val = (o & 1) ? (val * cs.x + partner * cs.y)
                              : (val * cs.x - partner * cs.y);
            }
            int h = o & 63;
            int n = o >> 6;
            dst[(((size_t)(bb * NH + n)) * L_ + l) * HD + h] = val;
        }
    }
}

__global__ __launch_bounds__(256) void gemm_out_kernel(
    const float* __restrict__ Wo, const float* __restrict__ bo,
    float* __restrict__ Y)
{
    __shared__ float Xs[GBM][GBK + 1];
    __shared__ float Ws[GBN][GBK + 1];

    GemmAcc A;
    gemm_core(g_Ctx, Wo, Xs, Ws, A);

    int tid = threadIdx.x;
    int tx = tid & 15, ty = tid >> 4;
    int m0 = blockIdx.y * GBM;
    int n0 = blockIdx.x * GBN;

    float bj[8];
    #pragma unroll
    for (int j = 0; j < 8; j++) bj[j] = bo[n0 + tx + 16 * j];

    #pragma unroll
    for (int i = 0; i < 8; i++) {
        int m = m0 + ty + 16 * i;
        #pragma unroll
        for (int j = 0; j < 8; j++) {
            int o = n0 + tx + 16 * j;
            Y[(size_t)m * D_ + o] = A.acc[i][j] + bj[j];
        }
    }
}

// ---------------------------------------------------------------------------
// Flash attention.  grid (L/64, B*NH), 256 threads.
// Q-tile 64 rows, K/V-tile 32 rows, fp32 online softmax.
// Thread (r = tid>>2, sub = tid&3):
//   S rows r, cols sub*8 .. sub*8+7
//   O rows r, head dims sub*16 .. sub*16+15
// ---------------------------------------------------------------------------
__global__ __launch_bounds__(256) void attn_kernel(const unsigned int* __restrict__ maskw)
{
    __shared__ float Qs[64][68];
    __shared__ float Ks[32][68];
    __shared__ float Vs[32][68];
    __shared__ float Ps[64][36];
    __shared__ unsigned int msk[32];

    int bh = blockIdx.y;          // 0..31
    int q0 = blockIdx.x * 64;
    int b  = bh >> 4;
    int n  = bh & 15;

    const float* Q = g_Qp + (size_t)bh * L_ * HD;
    const float* K = g_Kp + (size_t)bh * L_ * HD;
    const float* V = g_Vp + (size_t)bh * L_ * HD;

    int tid = threadIdx.x;
    int r   = tid >> 2;
    int sub = tid & 3;

    // load Q tile (vectorized)
    #pragma unroll
    for (int idx = tid; idx < 64 * 16; idx += 256) {
        int rr = idx >> 4;
        int h4 = (idx & 15) * 4;
        *(float4*)&Qs[rr][h4] = *(const float4*)&Q[(size_t)(q0 + rr) * HD + h4];
    }

    float m_i = -INFINITY;
    float l_i = 0.0f;
    float oa[16];
    #pragma unroll
    for (int j = 0; j < 16; j++) oa[j] = 0.0f;

    for (int kt = 0; kt < L_ / 32; kt++) {
        int k0 = kt * 32;
        __syncthreads();   // protect prev-iter Ks/Vs/Ps reads
        #pragma unroll
        for (int idx = tid; idx < 32 * 16; idx += 256) {
            int rr = idx >> 4;
            int h4 = (idx & 15) * 4;
            *(float4*)&Ks[rr][h4] = *(const float4*)&K[(size_t)(k0 + rr) * HD + h4];
            *(float4*)&Vs[rr][h4] = *(const float4*)&V[(size_t)(k0 + rr) * HD + h4];
        }
        if (tid < 32) msk[tid] = maskw[b * L_ + k0 + tid];
        __syncthreads();

        // S = Q K^T / 32
        float s[8];
        #pragma unroll
        for (int j = 0; j < 8; j++) s[j] = 0.0f;
        #pragma unroll
        for (int kk = 0; kk < HD; kk += 4) {
            float4 qv = *(const float4*)&Qs[r][kk];
            #pragma unroll
            for (int j = 0; j < 8; j++) {
                float4 kv = *(const float4*)&Ks[sub * 8 + j][kk];
                s[j] += qv.x * kv.x + qv.y * kv.y + qv.z * kv.z + qv.w * kv.w;
            }
        }

        float mloc = -INFINITY;
        #pragma unroll
        for (int j = 0; j < 8; j++) {
            s[j] = msk[sub * 8 + j] ? -1e8f : s[j] * 0.03125f;
            mloc = fmaxf(mloc, s[j]);
        }
        mloc = fmaxf(mloc, __shfl_xor_sync(0xffffffffu, mloc, 1));
        mloc = fmaxf(mloc, __shfl_xor_sync(0xffffffffu, mloc, 2));
        float m_new = fmaxf(m_i, mloc);
        float scale = expf(m_i - m_new);

        float lloc = 0.0f;
        #pragma unroll
        for (int j = 0; j < 8; j++) {
            s[j] = expf(s[j] - m_new);
            lloc += s[j];
        }
        lloc += __shfl_xor_sync(0xffffffffu, lloc, 1);
        lloc += __shfl_xor_sync(0xffffffffu, lloc, 2);
        l_i = l_i * scale + lloc;
        m_i = m_new;

        #pragma unroll
        for (int j = 0; j < 16; j++) oa[j] *= scale;

        *(float4*)&Ps[r][sub * 8 + 0] = make_float4(s[0], s[1], s[2], s[3]);
        *(float4*)&Ps[r][sub * 8 + 4] = make_float4(s[4], s[5], s[6], s[7]);
        __syncthreads();

        // O += P V
        #pragma unroll
        for (int cc = 0; cc < 32; cc += 4) {
            float4 pv = *(const float4*)&Ps[r][cc];
            #pragma unroll
            for (int mh = 0; mh < 4; mh++) {
                int h = sub * 16 + mh * 4;
                float4 v0 = *(const float4*)&Vs[cc + 0][h];
                float4 v1 = *(const float4*)&Vs[cc + 1][h];
                float4 v2 = *(const float4*)&Vs[cc + 2][h];
                float4 v3 = *(const float4*)&Vs[cc + 3][h];
                oa[mh * 4 + 0] += pv.x * v0.x + pv.y * v1.x + pv.z * v2.x + pv.w * v3.x;
                oa[mh * 4 + 1] += pv.x * v0.y + pv.y * v1.y + pv.z * v2.y + pv.w * v3.y;
                oa[mh * 4 + 2] += pv.x * v0.z + pv.y * v1.z + pv.z * v2.z + pv.w * v3.z;
                oa[mh * 4 + 3] += pv.x * v0.w + pv.y * v1.w + pv.z * v2.w + pv.w * v3.w;
            }
        }
    }

    float inv_l = 1.0f / l_i;
    int l = q0 + r;
    float* dst = g_Ctx + ((size_t)(b * L_ + l)) * D_ + n * HD + sub * 16;
    #pragma unroll
    for (int j = 0; j < 16; j += 4)
        *(float4*)(dst + j) = make_float4(oa[j] * inv_l, oa[j + 1] * inv_l,
                                          oa[j + 2] * inv_l, oa[j + 3] * inv_l);
}

// ---------------------------------------------------------------------------
// Inputs (metadata order): 0=q 1=k 2=v 3=mask 4=Wq 5=bq 6=Wk 7=bk 8=Wv 9=bv 10=Wo 11=bo
// ---------------------------------------------------------------------------
extern "C" void kernel_launch(void* const* d_in, const int* in_sizes, int n_in,
                              void* d_out, int out_size) {
    const float* q  = (const float*)d_in[0];
    const float* k  = (const float*)d_in[1];
    const float* v  = (const float*)d_in[2];
    const unsigned int* mask = (const unsigned int*)d_in[3];
    const float* Wq = (const float*)d_in[4];
    const float* bq = (const float*)d_in[5];
    const float* Wk = (const float*)d_in[6];
    const float* bk = (const float*)d_in[7];
    const float* Wv = (const float*)d_in[8];
    const float* bv = (const float*)d_in[9];
    const float* Wo = (const float*)d_in[10];
    const float* bo = (const float*)d_in[11];
    float* out = (float*)d_out;

    rope_table_kernel<<<(L_ * (HD / 2) + 255) / 256, 256>>>();
    gemm_qkv_kernel<<<dim3(D_ / GBN, M_ / GBM, 3), 256>>>(q, k, v, Wq, bq, Wk, bk, Wv, bv);
    attn_kernel<<<dim3(L_ / 64, B_ * NH), 256>>>(mask);
    gemm_out_kernel<<<dim3(D_ / GBN, M_ / GBM), 256>>>(Wo, bo, out);
}

// round 3
// speedup vs baseline: 3.1282x; 3.1282x over previous
#include <cuda_runtime.h>
#include <math.h>

// Problem constants
constexpr int B_  = 2;
constexpr int L_  = 2048;
constexpr int D_  = 1024;
constexpr int NH  = 16;
constexpr int HD  = 64;
constexpr int M_  = B_ * L_;     // 4096 rows for projections

// Scratch (device globals; no allocation allowed)
__device__ float  g_Qp[B_ * NH * L_ * HD];   // (b, n, l, h) roped
__device__ float  g_Kp[B_ * NH * L_ * HD];   // (b, n, l, h) roped
__device__ float  g_Vp[B_ * NH * L_ * HD];   // (b, n, l, h)
__device__ float  g_Ctx[B_ * L_ * D_];       // attention output (b, l, d)
__device__ float2 g_rope[L_ * (HD / 2)];     // (cos, sin) per (l, i)

// ---------------------------------------------------------------------------
// RoPE table
// ---------------------------------------------------------------------------
__global__ void rope_table_kernel() {
    int idx = blockIdx.x * blockDim.x + threadIdx.x;
    if (idx >= L_ * (HD / 2)) return;
    int l = idx >> 5;
    int i = idx & 31;
    float inv = powf(10000.0f, -(float)(2 * i) / 64.0f);
    float ang = (float)l * inv;
    float s, c;
    sincosf(ang, &s, &c);
    g_rope[idx] = make_float2(c, s);
}

// ---------------------------------------------------------------------------
// SGEMM: Y = X @ W^T + b.  (unchanged — measured near fp32 roofline)
// ---------------------------------------------------------------------------
#define GBM 128
#define GBN 128
#define GBK 16

struct GemmAcc {
    float acc[8][8];
};

__device__ __forceinline__ void gemm_core(
    const float* __restrict__ X, const float* __restrict__ W,
    float (&Xs)[GBM][GBK + 1], float (&Ws)[GBN][GBK + 1],
    GemmAcc& A)
{
    int tid = threadIdx.x;
    int tx = tid & 15, ty = tid >> 4;
    int m0 = blockIdx.y * GBM;
    int n0 = blockIdx.x * GBN;

    #pragma unroll
    for (int i = 0; i < 8; i++)
        #pragma unroll
        for (int j = 0; j < 8; j++)
            A.acc[i][j] = 0.0f;

    int lr = tid >> 1;           // 0..127
    int lc = (tid & 1) * 8;      // 0 or 8

    for (int k0 = 0; k0 < D_; k0 += GBK) {
        const float4* xp = (const float4*)(X + (size_t)(m0 + lr) * D_ + k0 + lc);
        const float4* wp = (const float4*)(W + (size_t)(n0 + lr) * D_ + k0 + lc);
        float4 xa = xp[0], xb = xp[1];
        float4 wa = wp[0], wb = wp[1];
        Xs[lr][lc + 0] = xa.x; Xs[lr][lc + 1] = xa.y; Xs[lr][lc + 2] = xa.z; Xs[lr][lc + 3] = xa.w;
        Xs[lr][lc + 4] = xb.x; Xs[lr][lc + 5] = xb.y; Xs[lr][lc + 6] = xb.z; Xs[lr][lc + 7] = xb.w;
        Ws[lr][lc + 0] = wa.x; Ws[lr][lc + 1] = wa.y; Ws[lr][lc + 2] = wa.z; Ws[lr][lc + 3] = wa.w;
        Ws[lr][lc + 4] = wb.x; Ws[lr][lc + 5] = wb.y; Ws[lr][lc + 6] = wb.z; Ws[lr][lc + 7] = wb.w;
        __syncthreads();

        #pragma unroll
        for (int kk = 0; kk < GBK; kk++) {
            float a[8], bb[8];
            #pragma unroll
            for (int i = 0; i < 8; i++) a[i] = Xs[ty + 16 * i][kk];
            #pragma unroll
            for (int j = 0; j < 8; j++) bb[j] = Ws[tx + 16 * j][kk];
            #pragma unroll
            for (int i = 0; i < 8; i++)
                #pragma unroll
                for (int j = 0; j < 8; j++)
                    A.acc[i][j] += a[i] * bb[j];
        }
        __syncthreads();
    }
}

__global__ __launch_bounds__(256) void gemm_qkv_kernel(
    const float* __restrict__ q, const float* __restrict__ k, const float* __restrict__ v,
    const float* __restrict__ Wq, const float* __restrict__ bq,
    const float* __restrict__ Wk, const float* __restrict__ bk,
    const float* __restrict__ Wv, const float* __restrict__ bv)
{
    __shared__ float Xs[GBM][GBK + 1];
    __shared__ float Ws[GBN][GBK + 1];

    int z = blockIdx.z;
    const float* X    = (z == 0) ? q  : (z == 1) ? k  : v;
    const float* W    = (z == 0) ? Wq : (z == 1) ? Wk : Wv;
    const float* bias = (z == 0) ? bq : (z == 1) ? bk : bv;
    float* dst        = (z == 0) ? g_Qp : (z == 1) ? g_Kp : g_Vp;

    GemmAcc A;
    gemm_core(X, W, Xs, Ws, A);

    int tid = threadIdx.x;
    int tx = tid & 15, ty = tid >> 4;
    int m0 = blockIdx.y * GBM;
    int n0 = blockIdx.x * GBN;

    float bj[8];
    #pragma unroll
    for (int j = 0; j < 8; j++) bj[j] = bias[n0 + tx + 16 * j];

    bool do_rope = (z < 2);

    #pragma unroll
    for (int i = 0; i < 8; i++) {
        int m = m0 + ty + 16 * i;
        int l = m & (L_ - 1);
        int bb = m >> 11;
        #pragma unroll
        for (int j = 0; j < 8; j++) {
            int o = n0 + tx + 16 * j;
            float val = A.acc[i][j] + bj[j];
            float partner = __shfl_xor_sync(0xffffffffu, val, 1);
            if (do_rope) {
                int h = o & 63;
                float2 cs = g_rope[(l << 5) + (h >> 1)];
                val = (o & 1) ? (val * cs.x + partner * cs.y)
                              : (val * cs.x - partner * cs.y);
            }
            int h = o & 63;
            int n = o >> 6;
            dst[(((size_t)(bb * NH + n)) * L_ + l) * HD + h] = val;
        }
    }
}

__global__ __launch_bounds__(256) void gemm_out_kernel(
    const float* __restrict__ Wo, const float* __restrict__ bo,
    float* __restrict__ Y)
{
    __shared__ float Xs[GBM][GBK + 1];
    __shared__ float Ws[GBN][GBK + 1];

    GemmAcc A;
    gemm_core(g_Ctx, Wo, Xs, Ws, A);

    int tid = threadIdx.x;
    int tx = tid & 15, ty = tid >> 4;
    int m0 = blockIdx.y * GBM;
    int n0 = blockIdx.x * GBN;

    float bj[8];
    #pragma unroll
    for (int j = 0; j < 8; j++) bj[j] = bo[n0 + tx + 16 * j];

    #pragma unroll
    for (int i = 0; i < 8; i++) {
        int m = m0 + ty + 16 * i;
        #pragma unroll
        for (int j = 0; j < 8; j++) {
            int o = n0 + tx + 16 * j;
            Y[(size_t)m * D_ + o] = A.acc[i][j] + bj[j];
        }
    }
}

// ---------------------------------------------------------------------------
// Flash attention, register-blocked.
// Grid (L/64, B*NH), 256 threads (16 tx x 16 ty).
// Q tile 64 rows, K/V tile 64 tokens.
// Each thread: 4 q-rows (ty + 16*i) x 4 k-cols (tx*4+jj), and 4 q-rows x
// 4 head-dims (tx*4+jj) of O.
// K stored transposed in smem (Kt[hd][token]) via in-register 4x4 transpose,
// so all mainloop LDS are broadcast or single-row float4 (conflict-free).
// ---------------------------------------------------------------------------
constexpr int AP = 68;                          // smem pitch (floats)
constexpr int ATT_SMEM = (4 * 64 * AP) * 4 + 64 * 4;  // Qs,Kt,Vs,Ps + mask

__global__ __launch_bounds__(256, 2) void attn_kernel(const unsigned int* __restrict__ maskw)
{
    extern __shared__ float sm[];
    float* Qs = sm;                   // [64][AP]  row = q-row, col = hd
    float* Kt = Qs + 64 * AP;         // [64][AP]  row = hd,   col = k-token
    float* Vs = Kt + 64 * AP;         // [64][AP]  row = k-token, col = hd
    float* Ps = Vs + 64 * AP;         // [64][AP]  row = q-row, col = k-token
    unsigned int* msk = (unsigned int*)(Ps + 64 * AP);

    int bh = blockIdx.y;              // 0..31
    int q0 = blockIdx.x * 64;
    int b  = bh >> 4;
    int n  = bh & 15;

    const float* Q = g_Qp + (size_t)bh * L_ * HD;
    const float* K = g_Kp + (size_t)bh * L_ * HD;
    const float* V = g_Vp + (size_t)bh * L_ * HD;

    int tid = threadIdx.x;
    int tx = tid & 15, ty = tid >> 4;

    // load Q tile (64 x 64)
    #pragma unroll
    for (int idx = tid; idx < 64 * 16; idx += 256) {
        int r = idx >> 4, c4 = (idx & 15) * 4;
        *(float4*)&Qs[r * AP + c4] = *(const float4*)&Q[(size_t)(q0 + r) * HD + c4];
    }

    float m_i[4], l_i[4], oa[4][4];
    #pragma unroll
    for (int i = 0; i < 4; i++) {
        m_i[i] = -INFINITY;
        l_i[i] = 0.0f;
        #pragma unroll
        for (int j = 0; j < 4; j++) oa[i][j] = 0.0f;
    }

    // K transpose block assignment: thread t handles 4x4 block
    int kbr = tid >> 4;   // token block row (0..15) -> tokens kbr*4..+3
    int kbc = tid & 15;   // hd block col (0..15)    -> hd kbc*4..+3

    for (int kt = 0; kt < L_ / 64; kt++) {
        int k0 = kt * 64;
        __syncthreads();   // previous iteration's Kt/Vs reads done

        // K: load 4x4 block, transpose in registers, store token-contiguous
        {
            float4 r0 = *(const float4*)&K[(size_t)(k0 + kbr * 4 + 0) * HD + kbc * 4];
            float4 r1 = *(const float4*)&K[(size_t)(k0 + kbr * 4 + 1) * HD + kbc * 4];
            float4 r2 = *(const float4*)&K[(size_t)(k0 + kbr * 4 + 2) * HD + kbc * 4];
            float4 r3 = *(const float4*)&K[(size_t)(k0 + kbr * 4 + 3) * HD + kbc * 4];
            *(float4*)&Kt[(kbc * 4 + 0) * AP + kbr * 4] = make_float4(r0.x, r1.x, r2.x, r3.x);
            *(float4*)&Kt[(kbc * 4 + 1) * AP + kbr * 4] = make_float4(r0.y, r1.y, r2.y, r3.y);
            *(float4*)&Kt[(kbc * 4 + 2) * AP + kbr * 4] = make_float4(r0.z, r1.z, r2.z, r3.z);
            *(float4*)&Kt[(kbc * 4 + 3) * AP + kbr * 4] = make_float4(r0.w, r1.w, r2.w, r3.w);
        }
        // V: direct
        #pragma unroll
        for (int idx = tid; idx < 64 * 16; idx += 256) {
            int r = idx >> 4, c4 = (idx & 15) * 4;
            *(float4*)&Vs[r * AP + c4] = *(const float4*)&V[(size_t)(k0 + r) * HD + c4];
        }
        if (tid < 64) msk[tid] = maskw[b * L_ + k0 + tid];
        __syncthreads();

        // ---- S = Q K^T ----
        float s[4][4];
        #pragma unroll
        for (int i = 0; i < 4; i++)
            #pragma unroll
            for (int j = 0; j < 4; j++) s[i][j] = 0.0f;

        #pragma unroll 4
        for (int kk = 0; kk < HD; kk += 4) {
            float4 qv[4], kv[4];
            #pragma unroll
            for (int i = 0; i < 4; i++) qv[i] = *(const float4*)&Qs[(ty + 16 * i) * AP + kk];
            #pragma unroll
            for (int c = 0; c < 4; c++) kv[c] = *(const float4*)&Kt[(kk + c) * AP + tx * 4];
            #pragma unroll
            for (int i = 0; i < 4; i++) {
                s[i][0] += qv[i].x * kv[0].x + qv[i].y * kv[1].x + qv[i].z * kv[2].x + qv[i].w * kv[3].x;
                s[i][1] += qv[i].x * kv[0].y + qv[i].y * kv[1].y + qv[i].z * kv[2].y + qv[i].w * kv[3].y;
                s[i][2] += qv[i].x * kv[0].z + qv[i].y * kv[1].z + qv[i].z * kv[2].z + qv[i].w * kv[3].z;
                s[i][3] += qv[i].x * kv[0].w + qv[i].y * kv[1].w + qv[i].z * kv[2].w + qv[i].w * kv[3].w;
            }
        }

        // ---- online softmax (rows = ty + 16*i, cols = tx*4+jj) ----
        unsigned int mk0 = msk[tx * 4 + 0];
        unsigned int mk1 = msk[tx * 4 + 1];
        unsigned int mk2 = msk[tx * 4 + 2];
        unsigned int mk3 = msk[tx * 4 + 3];

        #pragma unroll
        for (int i = 0; i < 4; i++) {
            float v0 = mk0 ? -1e8f : s[i][0] * 0.03125f;
            float v1 = mk1 ? -1e8f : s[i][1] * 0.03125f;
            float v2 = mk2 ? -1e8f : s[i][2] * 0.03125f;
            float v3 = mk3 ? -1e8f : s[i][3] * 0.03125f;
            float mloc = fmaxf(fmaxf(v0, v1), fmaxf(v2, v3));
            mloc = fmaxf(mloc, __shfl_xor_sync(0xffffffffu, mloc, 1));
            mloc = fmaxf(mloc, __shfl_xor_sync(0xffffffffu, mloc, 2));
            mloc = fmaxf(mloc, __shfl_xor_sync(0xffffffffu, mloc, 4));
            mloc = fmaxf(mloc, __shfl_xor_sync(0xffffffffu, mloc, 8));
            float m_new = fmaxf(m_i[i], mloc);
            float scale = __expf(m_i[i] - m_new);

            float p0 = __expf(v0 - m_new);
            float p1 = __expf(v1 - m_new);
            float p2 = __expf(v2 - m_new);
            float p3 = __expf(v3 - m_new);
            float lloc = p0 + p1 + p2 + p3;
            lloc += __shfl_xor_sync(0xffffffffu, lloc, 1);
            lloc += __shfl_xor_sync(0xffffffffu, lloc, 2);
            lloc += __shfl_xor_sync(0xffffffffu, lloc, 4);
            lloc += __shfl_xor_sync(0xffffffffu, lloc, 8);

            l_i[i] = l_i[i] * scale + lloc;
            m_i[i] = m_new;
            oa[i][0] *= scale; oa[i][1] *= scale; oa[i][2] *= scale; oa[i][3] *= scale;

            *(float4*)&Ps[(ty + 16 * i) * AP + tx * 4] = make_float4(p0, p1, p2, p3);
        }
        __syncwarp();   // P rows produced & consumed within the same half-warp

        // ---- O += P V ----
        #pragma unroll 4
        for (int cc = 0; cc < 64; cc += 4) {
            float4 pv[4], vv[4];
            #pragma unroll
            for (int i = 0; i < 4; i++) pv[i] = *(const float4*)&Ps[(ty + 16 * i) * AP + cc];
            #pragma unroll
            for (int c = 0; c < 4; c++) vv[c] = *(const float4*)&Vs[(cc + c) * AP + tx * 4];
            #pragma unroll
            for (int i = 0; i < 4; i++) {
                oa[i][0] += pv[i].x * vv[0].x + pv[i].y * vv[1].x + pv[i].z * vv[2].x + pv[i].w * vv[3].x;
                oa[i][1] += pv[i].x * vv[0].y + pv[i].y * vv[1].y + pv[i].z * vv[2].y + pv[i].w * vv[3].y;
                oa[i][2] += pv[i].x * vv[0].z + pv[i].y * vv[1].z + pv[i].z * vv[2].z + pv[i].w * vv[3].z;
                oa[i][3] += pv[i].x * vv[0].w + pv[i].y * vv[1].w + pv[i].z * vv[2].w + pv[i].w * vv[3].w;
            }
        }
    }

    #pragma unroll
    for (int i = 0; i < 4; i++) {
        float inv_l = 1.0f / l_i[i];
        int l = q0 + ty + 16 * i;
        float* dst = g_Ctx + ((size_t)(b * L_ + l)) * D_ + n * HD + tx * 4;
        *(float4*)dst = make_float4(oa[i][0] * inv_l, oa[i][1] * inv_l,
                                    oa[i][2] * inv_l, oa[i][3] * inv_l);
    }
}

// ---------------------------------------------------------------------------
// Inputs: 0=q 1=k 2=v 3=mask 4=Wq 5=bq 6=Wk 7=bk 8=Wv 9=bv 10=Wo 11=bo
// ---------------------------------------------------------------------------
extern "C" void kernel_launch(void* const* d_in, const int* in_sizes, int n_in,
                              void* d_out, int out_size) {
    const float* q  = (const float*)d_in[0];
    const float* k  = (const float*)d_in[1];
    const float* v  = (const float*)d_in[2];
    const unsigned int* mask = (const unsigned int*)d_in[3];
    const float* Wq = (const float*)d_in[4];
    const float* bq = (const float*)d_in[5];
    const float* Wk = (const float*)d_in[6];
    const float* bk = (const float*)d_in[7];
    const float* Wv = (const float*)d_in[8];
    const float* bv = (const float*)d_in[9];
    const float* Wo = (const float*)d_in[10];
    const float* bo = (const float*)d_in[11];
    float* out = (float*)d_out;

    cudaFuncSetAttribute(attn_kernel, cudaFuncAttributeMaxDynamicSharedMemorySize, ATT_SMEM);

    rope_table_kernel<<<(L_ * (HD / 2) + 255) / 256, 256>>>();
    gemm_qkv_kernel<<<dim3(D_ / GBN, M_ / GBM, 3), 256>>>(q, k, v, Wq, bq, Wk, bk, Wv, bv);
    attn_kernel<<<dim3(L_ / 64, B_ * NH), 256, ATT_SMEM>>>(mask);
    gemm_out_kernel<<<dim3(D_ / GBN, M_ / GBM), 256>>>(Wo, bo, out);
}

// round 9
// speedup vs baseline: 5.3694x; 1.7164x over previous
#include <cuda_runtime.h>
#include <cstdint>
#include <math.h>

// Problem constants
constexpr int B_  = 2;
constexpr int L_  = 2048;
constexpr int D_  = 1024;
constexpr int NH  = 16;
constexpr int HD  = 64;
constexpr int M_  = B_ * L_;     // 4096 rows for projections

// Scratch (device globals; no allocation allowed)
__device__ float  g_Qp[B_ * NH * L_ * HD];   // (b, n, l, h) roped
__device__ float  g_Kp[B_ * NH * L_ * HD];   // (b, n, l, h) roped
__device__ float  g_Vp[B_ * NH * L_ * HD];   // (b, n, l, h)
__device__ float  g_Ctx[B_ * L_ * D_];       // attention output (b, l, d)
__device__ float2 g_rope[L_ * (HD / 2)];     // (cos, sin) per (l, i)

// ---------------------------------------------------------------------------
// PTX helpers (mma.sync / ldmatrix / cp.async — all valid at target sm_103)
// ---------------------------------------------------------------------------
__device__ __forceinline__ uint32_t smem_u32(const void* p) {
    uint32_t a;
    asm("{ .reg .u64 t; cvta.to.shared.u64 t, %1; cvt.u32.u64 %0, t; }" : "=r"(a) : "l"(p));
    return a;
}

__device__ __forceinline__ void cp_async16(uint32_t saddr, const void* gaddr) {
    asm volatile("cp.async.cg.shared.global [%0], [%1], 16;" :: "r"(saddr), "l"(gaddr) : "memory");
}
__device__ __forceinline__ void cp_commit() {
    asm volatile("cp.async.commit_group;" ::: "memory");
}
template<int N> __device__ __forceinline__ void cp_wait() {
    asm volatile("cp.async.wait_group %0;" :: "n"(N) : "memory");
}

__device__ __forceinline__ void ldsm4(uint32_t& r0, uint32_t& r1, uint32_t& r2, uint32_t& r3,
                                      uint32_t addr) {
    asm volatile("ldmatrix.sync.aligned.m8n8.x4.shared.b16 {%0,%1,%2,%3}, [%4];"
                 : "=r"(r0), "=r"(r1), "=r"(r2), "=r"(r3) : "r"(addr));
}

__device__ __forceinline__ void cvt_tf32(uint32_t& r) {
    asm("cvt.rna.tf32.f32 %0, %0;" : "+r"(r));
}

__device__ __forceinline__ void mma_tf32(float* c, const uint32_t* a, const uint32_t* b) {
    asm volatile(
        "mma.sync.aligned.m16n8k8.row.col.f32.tf32.tf32.f32 "
        "{%0,%1,%2,%3}, {%4,%5,%6,%7}, {%8,%9}, {%0,%1,%2,%3};"
        : "+f"(c[0]), "+f"(c[1]), "+f"(c[2]), "+f"(c[3])
        : "r"(a[0]), "r"(a[1]), "r"(a[2]), "r"(a[3]), "r"(b[0]), "r"(b[1]));
}

// ---------------------------------------------------------------------------
// RoPE table
// ---------------------------------------------------------------------------
__global__ void rope_table_kernel() {
    int idx = blockIdx.x * blockDim.x + threadIdx.x;
    if (idx >= L_ * (HD / 2)) return;
    int l = idx >> 5;
    int i = idx & 31;
    float inv = powf(10000.0f, -(float)(2 * i) / 64.0f);
    float ang = (float)l * inv;
    float s, c;
    sincosf(ang, &s, &c);
    g_rope[idx] = make_float2(c, s);
}

// ---------------------------------------------------------------------------
// tf32 mma.sync GEMM core: acc[2][8][4] = X[m0:+128, :] @ W[n0:+128, :]^T
// 256 threads = 8 warps, warp grid 4(m) x 2(n), warp tile 32x64.
// BK=32, smem pitch 36 floats (conflict-free for ldmatrix), cp.async 2-stage.
// ---------------------------------------------------------------------------
constexpr int P_ = 36;                          // smem pitch (floats)
constexpr int TILE_BYTES  = 128 * P_ * 4;       // 18432
constexpr int STAGE_BYTES = 2 * TILE_BYTES;     // X + W
constexpr int GEMM_SMEM   = 2 * STAGE_BYTES;    // 73728

__device__ __forceinline__ void mma_proj_core(
    const float* __restrict__ X, const float* __restrict__ W,
    uint32_t sb, int m0, int n0, float acc[2][8][4])
{
    int tid = threadIdx.x;

    #pragma unroll
    for (int mf = 0; mf < 2; mf++)
        #pragma unroll
        for (int nf = 0; nf < 8; nf++)
            #pragma unroll
            for (int r = 0; r < 4; r++) acc[mf][nf][r] = 0.0f;

    // loader: thread covers rows (tid>>3) + 32*i, float col (tid&7)*4
    const int lrow = tid >> 3;
    const int lcol = (tid & 7) * 4;
    const float* Xg = X + (size_t)(m0 + lrow) * D_ + lcol;
    const float* Wg = W + (size_t)(n0 + lrow) * D_ + lcol;
    const uint32_t sX = sb + (lrow * P_ + lcol) * 4;
    const uint32_t sW = sX + TILE_BYTES;

    // fragment lane geometry
    const int lane = tid & 31;
    const int wm = (tid >> 5) & 3;      // warp m index (0..3)
    const int wn = tid >> 7;            // warp n index (0..1)
    const int arow = lane & 15;
    const int acol = (lane >> 4) * 4;
    const int brow = lane & 7;
    const int bcol = ((lane >> 3) & 1) * 4;
    const int bhi  = (lane >> 4) * 8;

    // prologue: stage 0 = k-block 0
    #pragma unroll
    for (int i = 0; i < 4; i++) {
        cp_async16(sX + i * 32 * P_ * 4, Xg + (size_t)i * 32 * D_);
        cp_async16(sW + i * 32 * P_ * 4, Wg + (size_t)i * 32 * D_);
    }
    cp_commit();

    for (int it = 0; it < 32; it++) {
        int s = it & 1;
        if (it < 31) {
            uint32_t off = ((it + 1) & 1) * STAGE_BYTES;
            int k0 = (it + 1) * 32;
            #pragma unroll
            for (int i = 0; i < 4; i++) {
                cp_async16(sX + off + i * 32 * P_ * 4, Xg + k0 + (size_t)i * 32 * D_);
                cp_async16(sW + off + i * 32 * P_ * 4, Wg + k0 + (size_t)i * 32 * D_);
            }
            cp_commit();
            cp_wait<1>();
        } else {
            cp_wait<0>();
        }
        __syncthreads();

        uint32_t xb = sb + s * STAGE_BYTES;
        uint32_t wb = xb + TILE_BYTES;

        #pragma unroll
        for (int ks = 0; ks < 4; ks++) {
            int kc = ks * 8;
            uint32_t a[2][4];
            #pragma unroll
            for (int mf = 0; mf < 2; mf++) {
                uint32_t addr = xb + ((wm * 32 + mf * 16 + arow) * P_ + kc + acol) * 4;
                ldsm4(a[mf][0], a[mf][1], a[mf][2], a[mf][3], addr);
                cvt_tf32(a[mf][0]); cvt_tf32(a[mf][1]); cvt_tf32(a[mf][2]); cvt_tf32(a[mf][3]);
            }
            uint32_t b[8][2];
            #pragma unroll
            for (int nf2 = 0; nf2 < 4; nf2++) {
                uint32_t addr = wb + ((wn * 64 + nf2 * 16 + bhi + brow) * P_ + kc + bcol) * 4;
                uint32_t r0, r1, r2, r3;
                ldsm4(r0, r1, r2, r3, addr);
                cvt_tf32(r0); cvt_tf32(r1); cvt_tf32(r2); cvt_tf32(r3);
                b[nf2 * 2][0] = r0; b[nf2 * 2][1] = r1;
                b[nf2 * 2 + 1][0] = r2; b[nf2 * 2 + 1][1] = r3;
            }
            #pragma unroll
            for (int mf = 0; mf < 2; mf++)
                #pragma unroll
                for (int nf = 0; nf < 8; nf++)
                    mma_tf32(acc[mf][nf], a[mf], b[nf]);
        }
        __syncthreads();
    }
}

// ---------------------------------------------------------------------------
// QKV projection: grid (8, 32, 3). Epilogue: bias + RoPE (z<2) + scatter to
// (b, n, l, h). C-frag cols (c0,c1)/(c2,c3) are the even/odd RoPE pairs.
// ---------------------------------------------------------------------------
__global__ __launch_bounds__(256, 2) void mma_qkv_kernel(
    const float* __restrict__ q, const float* __restrict__ k, const float* __restrict__ v,
    const float* __restrict__ Wq, const float* __restrict__ bq,
    const float* __restrict__ Wk, const float* __restrict__ bk,
    const float* __restrict__ Wv, const float* __restrict__ bv)
{
    extern __shared__ float sm[];
    uint32_t sb = smem_u32(sm);

    int z = blockIdx.z;
    const float* X    = (z == 0) ? q  : (z == 1) ? k  : v;
    const float* W    = (z == 0) ? Wq : (z == 1) ? Wk : Wv;
    const float* bias = (z == 0) ? bq : (z == 1) ? bk : bv;
    float* dstb       = (z == 0) ? g_Qp : (z == 1) ? g_Kp : g_Vp;
    bool do_rope = (z < 2);

    int m0 = blockIdx.y * 128;
    int n0 = blockIdx.x * 128;

    float acc[2][8][4];
    mma_proj_core(X, W, sb, m0, n0, acc);

    int tid = threadIdx.x;
    int lane = tid & 31;
    int wm = (tid >> 5) & 3;
    int wn = tid >> 7;
    int g = lane >> 2, tq = lane & 3;

    #pragma unroll
    for (int mf = 0; mf < 2; mf++) {
        #pragma unroll
        for (int rr = 0; rr < 2; rr++) {
            int m = m0 + wm * 32 + mf * 16 + g + rr * 8;
            int l = m & (L_ - 1);
            int bb = m >> 11;
            #pragma unroll
            for (int nf = 0; nf < 8; nf++) {
                int col = n0 + wn * 64 + nf * 8 + tq * 2;
                float2 b2 = *(const float2*)&bias[col];
                float c0 = acc[mf][nf][rr * 2 + 0] + b2.x;
                float c1 = acc[mf][nf][rr * 2 + 1] + b2.y;
                int h = col & 63;
                if (do_rope) {
                    float2 cs = g_rope[(l << 5) + (h >> 1)];
                    float e = c0, o = c1;
                    c0 = e * cs.x - o * cs.y;
                    c1 = o * cs.x + e * cs.y;
                }
                int n = col >> 6;
                float* dst = dstb + (((size_t)(bb * NH + n)) * L_ + l) * HD + h;
                *(float2*)dst = make_float2(c0, c1);
            }
        }
    }
}

// ---------------------------------------------------------------------------
// Output projection: grid (8, 32). Y = g_Ctx @ Wo^T + bo, row-major.
// ---------------------------------------------------------------------------
__global__ __launch_bounds__(256, 2) void mma_out_kernel(
    const float* __restrict__ Wo, const float* __restrict__ bo,
    float* __restrict__ Y)
{
    extern __shared__ float sm[];
    uint32_t sb = smem_u32(sm);

    int m0 = blockIdx.y * 128;
    int n0 = blockIdx.x * 128;

    float acc[2][8][4];
    mma_proj_core(g_Ctx, Wo, sb, m0, n0, acc);

    int tid = threadIdx.x;
    int lane = tid & 31;
    int wm = (tid >> 5) & 3;
    int wn = tid >> 7;
    int g = lane >> 2, tq = lane & 3;

    #pragma unroll
    for (int mf = 0; mf < 2; mf++) {
        #pragma unroll
        for (int rr = 0; rr < 2; rr++) {
            int m = m0 + wm * 32 + mf * 16 + g + rr * 8;
            #pragma unroll
            for (int nf = 0; nf < 8; nf++) {
                int col = n0 + wn * 64 + nf * 8 + tq * 2;
                float2 b2 = *(const float2*)&bo[col];
                *(float2*)&Y[(size_t)m * D_ + col] =
                    make_float2(acc[mf][nf][rr * 2 + 0] + b2.x,
                                acc[mf][nf][rr * 2 + 1] + b2.y);
            }
        }
    }
}

// ---------------------------------------------------------------------------
// Flash attention, register-blocked (unchanged — passing at ~970us)
// ---------------------------------------------------------------------------
constexpr int AP = 68;                                // smem pitch (floats)
constexpr int ATT_SMEM = (4 * 64 * AP) * 4 + 64 * 4;  // Qs,Kt,Vs,Ps + mask

__global__ __launch_bounds__(256, 2) void attn_kernel(const unsigned int* __restrict__ maskw)
{
    extern __shared__ float smf[];
    float* Qs = smf;                  // [64][AP]  row = q-row, col = hd
    float* Kt = Qs + 64 * AP;         // [64][AP]  row = hd,   col = k-token
    float* Vs = Kt + 64 * AP;         // [64][AP]  row = k-token, col = hd
    float* Ps = Vs + 64 * AP;         // [64][AP]  row = q-row, col = k-token
    unsigned int* msk = (unsigned int*)(Ps + 64 * AP);

    int bh = blockIdx.y;
    int q0 = blockIdx.x * 64;
    int b  = bh >> 4;
    int n  = bh & 15;

    const float* Q = g_Qp + (size_t)bh * L_ * HD;
    const float* K = g_Kp + (size_t)bh * L_ * HD;
    const float* V = g_Vp + (size_t)bh * L_ * HD;

    int tid = threadIdx.x;
    int tx = tid & 15, ty = tid >> 4;

    #pragma unroll
    for (int idx = tid; idx < 64 * 16; idx += 256) {
        int r = idx >> 4, c4 = (idx & 15) * 4;
        *(float4*)&Qs[r * AP + c4] = *(const float4*)&Q[(size_t)(q0 + r) * HD + c4];
    }

    float m_i[4], l_i[4], oa[4][4];
    #pragma unroll
    for (int i = 0; i < 4; i++) {
        m_i[i] = -INFINITY;
        l_i[i] = 0.0f;
        #pragma unroll
        for (int j = 0; j < 4; j++) oa[i][j] = 0.0f;
    }

    int kbr = tid >> 4;
    int kbc = tid & 15;

    for (int kt = 0; kt < L_ / 64; kt++) {
        int k0 = kt * 64;
        __syncthreads();

        {
            float4 r0 = *(const float4*)&K[(size_t)(k0 + kbr * 4 + 0) * HD + kbc * 4];
            float4 r1 = *(const float4*)&K[(size_t)(k0 + kbr * 4 + 1) * HD + kbc * 4];
            float4 r2 = *(const float4*)&K[(size_t)(k0 + kbr * 4 + 2) * HD + kbc * 4];
            float4 r3 = *(const float4*)&K[(size_t)(k0 + kbr * 4 + 3) * HD + kbc * 4];
            *(float4*)&Kt[(kbc * 4 + 0) * AP + kbr * 4] = make_float4(r0.x, r1.x, r2.x, r3.x);
            *(float4*)&Kt[(kbc * 4 + 1) * AP + kbr * 4] = make_float4(r0.y, r1.y, r2.y, r3.y);
            *(float4*)&Kt[(kbc * 4 + 2) * AP + kbr * 4] = make_float4(r0.z, r1.z, r2.z, r3.z);
            *(float4*)&Kt[(kbc * 4 + 3) * AP + kbr * 4] = make_float4(r0.w, r1.w, r2.w, r3.w);
        }
        #pragma unroll
        for (int idx = tid; idx < 64 * 16; idx += 256) {
            int r = idx >> 4, c4 = (idx & 15) * 4;
            *(float4*)&Vs[r * AP + c4] = *(const float4*)&V[(size_t)(k0 + r) * HD + c4];
        }
        if (tid < 64) msk[tid] = maskw[b * L_ + k0 + tid];
        __syncthreads();

        float s[4][4];
        #pragma unroll
        for (int i = 0; i < 4; i++)
            #pragma unroll
            for (int j = 0; j < 4; j++) s[i][j] = 0.0f;

        #pragma unroll 4
        for (int kk = 0; kk < HD; kk += 4) {
            float4 qv[4], kv[4];
            #pragma unroll
            for (int i = 0; i < 4; i++) qv[i] = *(const float4*)&Qs[(ty + 16 * i) * AP + kk];
            #pragma unroll
            for (int c = 0; c < 4; c++) kv[c] = *(const float4*)&Kt[(kk + c) * AP + tx * 4];
            #pragma unroll
            for (int i = 0; i < 4; i++) {
                s[i][0] += qv[i].x * kv[0].x + qv[i].y * kv[1].x + qv[i].z * kv[2].x + qv[i].w * kv[3].x;
                s[i][1] += qv[i].x * kv[0].y + qv[i].y * kv[1].y + qv[i].z * kv[2].y + qv[i].w * kv[3].y;
                s[i][2] += qv[i].x * kv[0].z + qv[i].y * kv[1].z + qv[i].z * kv[2].z + qv[i].w * kv[3].z;
                s[i][3] += qv[i].x * kv[0].w + qv[i].y * kv[1].w + qv[i].z * kv[2].w + qv[i].w * kv[3].w;
            }
        }

        unsigned int mk0 = msk[tx * 4 + 0];
        unsigned int mk1 = msk[tx * 4 + 1];
        unsigned int mk2 = msk[tx * 4 + 2];
        unsigned int mk3 = msk[tx * 4 + 3];

        #pragma unroll
        for (int i = 0; i < 4; i++) {
            float v0 = mk0 ? -1e8f : s[i][0] * 0.03125f;
            float v1 = mk1 ? -1e8f : s[i][1] * 0.03125f;
            float v2 = mk2 ? -1e8f : s[i][2] * 0.03125f;
            float v3 = mk3 ? -1e8f : s[i][3] * 0.03125f;
            float mloc = fmaxf(fmaxf(v0, v1), fmaxf(v2, v3));
            mloc = fmaxf(mloc, __shfl_xor_sync(0xffffffffu, mloc, 1));
            mloc = fmaxf(mloc, __shfl_xor_sync(0xffffffffu, mloc, 2));
            mloc = fmaxf(mloc, __shfl_xor_sync(0xffffffffu, mloc, 4));
            mloc = fmaxf(mloc, __shfl_xor_sync(0xffffffffu, mloc, 8));
            float m_new = fmaxf(m_i[i], mloc);
            float scale = __expf(m_i[i] - m_new);

            float p0 = __expf(v0 - m_new);
            float p1 = __expf(v1 - m_new);
            float p2 = __expf(v2 - m_new);
            float p3 = __expf(v3 - m_new);
            float lloc = p0 + p1 + p2 + p3;
            lloc += __shfl_xor_sync(0xffffffffu, lloc, 1);
            lloc += __shfl_xor_sync(0xffffffffu, lloc, 2);
            lloc += __shfl_xor_sync(0xffffffffu, lloc, 4);
            lloc += __shfl_xor_sync(0xffffffffu, lloc, 8);

            l_i[i] = l_i[i] * scale + lloc;
            m_i[i] = m_new;
            oa[i][0] *= scale; oa[i][1] *= scale; oa[i][2] *= scale; oa[i][3] *= scale;

            *(float4*)&Ps[(ty + 16 * i) * AP + tx * 4] = make_float4(p0, p1, p2, p3);
        }
        __syncwarp();

        #pragma unroll 4
        for (int cc = 0; cc < 64; cc += 4) {
            float4 pv[4], vv[4];
            #pragma unroll
            for (int i = 0; i < 4; i++) pv[i] = *(const float4*)&Ps[(ty + 16 * i) * AP + cc];
            #pragma unroll
            for (int c = 0; c < 4; c++) vv[c] = *(const float4*)&Vs[(cc + c) * AP + tx * 4];
            #pragma unroll
            for (int i = 0; i < 4; i++) {
                oa[i][0] += pv[i].x * vv[0].x + pv[i].y * vv[1].x + pv[i].z * vv[2].x + pv[i].w * vv[3].x;
                oa[i][1] += pv[i].x * vv[0].y + pv[i].y * vv[1].y + pv[i].z * vv[2].y + pv[i].w * vv[3].y;
                oa[i][2] += pv[i].x * vv[0].z + pv[i].y * vv[1].z + pv[i].z * vv[2].z + pv[i].w * vv[3].z;
                oa[i][3] += pv[i].x * vv[0].w + pv[i].y * vv[1].w + pv[i].z * vv[2].w + pv[i].w * vv[3].w;
            }
        }
    }

    #pragma unroll
    for (int i = 0; i < 4; i++) {
        float inv_l = 1.0f / l_i[i];
        int l = q0 + ty + 16 * i;
        float* dst = g_Ctx + ((size_t)(b * L_ + l)) * D_ + n * HD + tx * 4;
        *(float4*)dst = make_float4(oa[i][0] * inv_l, oa[i][1] * inv_l,
                                    oa[i][2] * inv_l, oa[i][3] * inv_l);
    }
}

// ---------------------------------------------------------------------------
// Inputs: 0=q 1=k 2=v 3=mask 4=Wq 5=bq 6=Wk 7=bk 8=Wv 9=bv 10=Wo 11=bo
// ---------------------------------------------------------------------------
extern "C" void kernel_launch(void* const* d_in, const int* in_sizes, int n_in,
                              void* d_out, int out_size) {
    const float* q  = (const float*)d_in[0];
    const float* k  = (const float*)d_in[1];
    const float* v  = (const float*)d_in[2];
    const unsigned int* mask = (const unsigned int*)d_in[3];
    const float* Wq = (const float*)d_in[4];
    const float* bq = (const float*)d_in[5];
    const float* Wk = (const float*)d_in[6];
    const float* bk = (const float*)d_in[7];
    const float* Wv = (const float*)d_in[8];
    const float* bv = (const float*)d_in[9];
    const float* Wo = (const float*)d_in[10];
    const float* bo = (const float*)d_in[11];
    float* out = (float*)d_out;

    cudaFuncSetAttribute(attn_kernel, cudaFuncAttributeMaxDynamicSharedMemorySize, ATT_SMEM);
    cudaFuncSetAttribute(mma_qkv_kernel, cudaFuncAttributeMaxDynamicSharedMemorySize, GEMM_SMEM);
    cudaFuncSetAttribute(mma_out_kernel, cudaFuncAttributeMaxDynamicSharedMemorySize, GEMM_SMEM);

    rope_table_kernel<<<(L_ * (HD / 2) + 255) / 256, 256>>>();
    mma_qkv_kernel<<<dim3(D_ / 128, M_ / 128, 3), 256, GEMM_SMEM>>>(
        q, k, v, Wq, bq, Wk, bk, Wv, bv);
    attn_kernel<<<dim3(L_ / 64, B_ * NH), 256, ATT_SMEM>>>(mask);
    mma_out_kernel<<<dim3(D_ / 128, M_ / 128), 256, GEMM_SMEM>>>(Wo, bo, out);
}

// round 10
// speedup vs baseline: 10.5076x; 1.9569x over previous
#include <cuda_runtime.h>
#include <cstdint>
#include <math.h>

// Problem constants
constexpr int B_  = 2;
constexpr int L_  = 2048;
constexpr int D_  = 1024;
constexpr int NH  = 16;
constexpr int HD  = 64;
constexpr int M_  = B_ * L_;     // 4096 rows for projections

// Scratch (device globals; no allocation allowed)
__device__ float  g_Qp[B_ * NH * L_ * HD];   // (b, n, l, h) roped
__device__ float  g_Kp[B_ * NH * L_ * HD];   // (b, n, l, h) roped
__device__ float  g_Vp[B_ * NH * L_ * HD];   // (b, n, l, h)
__device__ float  g_Ctx[B_ * L_ * D_];       // attention output (b, l, d)
__device__ float2 g_rope[L_ * (HD / 2)];     // (cos, sin) per (l, i)

// ---------------------------------------------------------------------------
// PTX helpers (mma.sync / ldmatrix / cp.async — all valid at target sm_103)
// ---------------------------------------------------------------------------
__device__ __forceinline__ uint32_t smem_u32(const void* p) {
    uint32_t a;
    asm("{ .reg .u64 t; cvta.to.shared.u64 t, %1; cvt.u32.u64 %0, t; }" : "=r"(a) : "l"(p));
    return a;
}

__device__ __forceinline__ void cp_async16(uint32_t saddr, const void* gaddr) {
    asm volatile("cp.async.cg.shared.global [%0], [%1], 16;" :: "r"(saddr), "l"(gaddr) : "memory");
}
__device__ __forceinline__ void cp_commit() {
    asm volatile("cp.async.commit_group;" ::: "memory");
}
template<int N> __device__ __forceinline__ void cp_wait() {
    asm volatile("cp.async.wait_group %0;" :: "n"(N) : "memory");
}

__device__ __forceinline__ void ldsm4(uint32_t& r0, uint32_t& r1, uint32_t& r2, uint32_t& r3,
                                      uint32_t addr) {
    asm volatile("ldmatrix.sync.aligned.m8n8.x4.shared.b16 {%0,%1,%2,%3}, [%4];"
                 : "=r"(r0), "=r"(r1), "=r"(r2), "=r"(r3) : "r"(addr));
}

__device__ __forceinline__ void cvt_tf32(uint32_t& r) {
    asm("cvt.rna.tf32.f32 %0, %0;" : "+r"(r));
}

__device__ __forceinline__ void mma_tf32(float* c, const uint32_t* a, const uint32_t* b) {
    asm volatile(
        "mma.sync.aligned.m16n8k8.row.col.f32.tf32.tf32.f32 "
        "{%0,%1,%2,%3}, {%4,%5,%6,%7}, {%8,%9}, {%0,%1,%2,%3};"
        : "+f"(c[0]), "+f"(c[1]), "+f"(c[2]), "+f"(c[3])
        : "r"(a[0]), "r"(a[1]), "r"(a[2]), "r"(a[3]), "r"(b[0]), "r"(b[1]));
}

// ---------------------------------------------------------------------------
// RoPE table
// ---------------------------------------------------------------------------
__global__ void rope_table_kernel() {
    int idx = blockIdx.x * blockDim.x + threadIdx.x;
    if (idx >= L_ * (HD / 2)) return;
    int l = idx >> 5;
    int i = idx & 31;
    float inv = powf(10000.0f, -(float)(2 * i) / 64.0f);
    float ang = (float)l * inv;
    float s, c;
    sincosf(ang, &s, &c);
    g_rope[idx] = make_float2(c, s);
}

// ---------------------------------------------------------------------------
// tf32 mma.sync GEMM core (projections) — unchanged from R9
// ---------------------------------------------------------------------------
constexpr int P_ = 36;                          // smem pitch (floats)
constexpr int TILE_BYTES  = 128 * P_ * 4;       // 18432
constexpr int STAGE_BYTES = 2 * TILE_BYTES;     // X + W
constexpr int GEMM_SMEM   = 2 * STAGE_BYTES;    // 73728

__device__ __forceinline__ void mma_proj_core(
    const float* __restrict__ X, const float* __restrict__ W,
    uint32_t sb, int m0, int n0, float acc[2][8][4])
{
    int tid = threadIdx.x;

    #pragma unroll
    for (int mf = 0; mf < 2; mf++)
        #pragma unroll
        for (int nf = 0; nf < 8; nf++)
            #pragma unroll
            for (int r = 0; r < 4; r++) acc[mf][nf][r] = 0.0f;

    const int lrow = tid >> 3;
    const int lcol = (tid & 7) * 4;
    const float* Xg = X + (size_t)(m0 + lrow) * D_ + lcol;
    const float* Wg = W + (size_t)(n0 + lrow) * D_ + lcol;
    const uint32_t sX = sb + (lrow * P_ + lcol) * 4;
    const uint32_t sW = sX + TILE_BYTES;

    const int lane = tid & 31;
    const int wm = (tid >> 5) & 3;
    const int wn = tid >> 7;
    const int arow = lane & 15;
    const int acol = (lane >> 4) * 4;
    const int brow = lane & 7;
    const int bcol = ((lane >> 3) & 1) * 4;
    const int bhi  = (lane >> 4) * 8;

    #pragma unroll
    for (int i = 0; i < 4; i++) {
        cp_async16(sX + i * 32 * P_ * 4, Xg + (size_t)i * 32 * D_);
        cp_async16(sW + i * 32 * P_ * 4, Wg + (size_t)i * 32 * D_);
    }
    cp_commit();

    for (int it = 0; it < 32; it++) {
        int s = it & 1;
        if (it < 31) {
            uint32_t off = ((it + 1) & 1) * STAGE_BYTES;
            int k0 = (it + 1) * 32;
            #pragma unroll
            for (int i = 0; i < 4; i++) {
                cp_async16(sX + off + i * 32 * P_ * 4, Xg + k0 + (size_t)i * 32 * D_);
                cp_async16(sW + off + i * 32 * P_ * 4, Wg + k0 + (size_t)i * 32 * D_);
            }
            cp_commit();
            cp_wait<1>();
        } else {
            cp_wait<0>();
        }
        __syncthreads();

        uint32_t xb = sb + s * STAGE_BYTES;
        uint32_t wb = xb + TILE_BYTES;

        #pragma unroll
        for (int ks = 0; ks < 4; ks++) {
            int kc = ks * 8;
            uint32_t a[2][4];
            #pragma unroll
            for (int mf = 0; mf < 2; mf++) {
                uint32_t addr = xb + ((wm * 32 + mf * 16 + arow) * P_ + kc + acol) * 4;
                ldsm4(a[mf][0], a[mf][1], a[mf][2], a[mf][3], addr);
                cvt_tf32(a[mf][0]); cvt_tf32(a[mf][1]); cvt_tf32(a[mf][2]); cvt_tf32(a[mf][3]);
            }
            uint32_t b[8][2];
            #pragma unroll
            for (int nf2 = 0; nf2 < 4; nf2++) {
                uint32_t addr = wb + ((wn * 64 + nf2 * 16 + bhi + brow) * P_ + kc + bcol) * 4;
                uint32_t r0, r1, r2, r3;
                ldsm4(r0, r1, r2, r3, addr);
                cvt_tf32(r0); cvt_tf32(r1); cvt_tf32(r2); cvt_tf32(r3);
                b[nf2 * 2][0] = r0; b[nf2 * 2][1] = r1;
                b[nf2 * 2 + 1][0] = r2; b[nf2 * 2 + 1][1] = r3;
            }
            #pragma unroll
            for (int mf = 0; mf < 2; mf++)
                #pragma unroll
                for (int nf = 0; nf < 8; nf++)
                    mma_tf32(acc[mf][nf], a[mf], b[nf]);
        }
        __syncthreads();
    }
}

__global__ __launch_bounds__(256, 2) void mma_qkv_kernel(
    const float* __restrict__ q, const float* __restrict__ k, const float* __restrict__ v,
    const float* __restrict__ Wq, const float* __restrict__ bq,
    const float* __restrict__ Wk, const float* __restrict__ bk,
    const float* __restrict__ Wv, const float* __restrict__ bv)
{
    extern __shared__ float sm[];
    uint32_t sb = smem_u32(sm);

    int z = blockIdx.z;
    const float* X    = (z == 0) ? q  : (z == 1) ? k  : v;
    const float* W    = (z == 0) ? Wq : (z == 1) ? Wk : Wv;
    const float* bias = (z == 0) ? bq : (z == 1) ? bk : bv;
    float* dstb       = (z == 0) ? g_Qp : (z == 1) ? g_Kp : g_Vp;
    bool do_rope = (z < 2);

    int m0 = blockIdx.y * 128;
    int n0 = blockIdx.x * 128;

    float acc[2][8][4];
    mma_proj_core(X, W, sb, m0, n0, acc);

    int tid = threadIdx.x;
    int lane = tid & 31;
    int wm = (tid >> 5) & 3;
    int wn = tid >> 7;
    int g = lane >> 2, tq = lane & 3;

    #pragma unroll
    for (int mf = 0; mf < 2; mf++) {
        #pragma unroll
        for (int rr = 0; rr < 2; rr++) {
            int m = m0 + wm * 32 + mf * 16 + g + rr * 8;
            int l = m & (L_ - 1);
            int bb = m >> 11;
            #pragma unroll
            for (int nf = 0; nf < 8; nf++) {
                int col = n0 + wn * 64 + nf * 8 + tq * 2;
                float2 b2 = *(const float2*)&bias[col];
                float c0 = acc[mf][nf][rr * 2 + 0] + b2.x;
                float c1 = acc[mf][nf][rr * 2 + 1] + b2.y;
                int h = col & 63;
                if (do_rope) {
                    float2 cs = g_rope[(l << 5) + (h >> 1)];
                    float e = c0, o = c1;
                    c0 = e * cs.x - o * cs.y;
                    c1 = o * cs.x + e * cs.y;
                }
                int n = col >> 6;
                float* dst = dstb + (((size_t)(bb * NH + n)) * L_ + l) * HD + h;
                *(float2*)dst = make_float2(c0, c1);
            }
        }
    }
}

__global__ __launch_bounds__(256, 2) void mma_out_kernel(
    const float* __restrict__ Wo, const float* __restrict__ bo,
    float* __restrict__ Y)
{
    extern __shared__ float sm[];
    uint32_t sb = smem_u32(sm);

    int m0 = blockIdx.y * 128;
    int n0 = blockIdx.x * 128;

    float acc[2][8][4];
    mma_proj_core(g_Ctx, Wo, sb, m0, n0, acc);

    int tid = threadIdx.x;
    int lane = tid & 31;
    int wm = (tid >> 5) & 3;
    int wn = tid >> 7;
    int g = lane >> 2, tq = lane & 3;

    #pragma unroll
    for (int mf = 0; mf < 2; mf++) {
        #pragma unroll
        for (int rr = 0; rr < 2; rr++) {
            int m = m0 + wm * 32 + mf * 16 + g + rr * 8;
            #pragma unroll
            for (int nf = 0; nf < 8; nf++) {
                int col = n0 + wn * 64 + nf * 8 + tq * 2;
                float2 b2 = *(const float2*)&bo[col];
                *(float2*)&Y[(size_t)m * D_ + col] =
                    make_float2(acc[mf][nf][rr * 2 + 0] + b2.x,
                                acc[mf][nf][rr * 2 + 1] + b2.y);
            }
        }
    }
}

// ---------------------------------------------------------------------------
// Flash attention via tf32 mma.sync.
// Grid (L/64, B*NH), 128 threads = 4 warps; warp w owns q-rows w*16..+15.
// K-tile = 64 tokens. Q A-frags preloaded to registers.
// S = Q@K^T: B-operand is K[token][h] directly (n=token, k=h).
// O += P@V: A from Ps (smem round-trip), B from Vt (V transposed, n=h, k=token).
// Smem pitch 68 floats -> ldmatrix conflict-free.
// ---------------------------------------------------------------------------
constexpr int AAP = 68;
constexpr int ATT_SMEM = (3 * 64 * AAP) * 4 + 64 * 4;  // Ks, Vt, Ps + mask
constexpr float SCALE_ = 0.03125f;                     // 1/sqrt(1024)

__global__ __launch_bounds__(128) void attn_mma_kernel(const unsigned int* __restrict__ maskw)
{
    extern __shared__ float smf[];
    float* Ks = smf;                  // [64][AAP] row = token, col = hd
    float* Vt = Ks + 64 * AAP;        // [64][AAP] row = hd,   col = token
    float* Ps = Vt + 64 * AAP;        // [64][AAP] row = q-row, col = token (also Q staging)
    unsigned int* msk = (unsigned int*)(Ps + 64 * AAP);

    const uint32_t sKs = smem_u32(Ks);
    const uint32_t sVt = smem_u32(Vt);
    const uint32_t sPs = smem_u32(Ps);

    int bh = blockIdx.y;
    int q0 = blockIdx.x * 64;
    int b  = bh >> 4;
    int n  = bh & 15;

    const float* Q = g_Qp + (size_t)bh * L_ * HD;
    const float* K = g_Kp + (size_t)bh * L_ * HD;
    const float* V = g_Vp + (size_t)bh * L_ * HD;

    int tid  = threadIdx.x;
    int lane = tid & 31;
    int w    = tid >> 5;              // warp 0..3
    int g    = lane >> 2, tq = lane & 3;
    int arow = lane & 15;
    int acol = (lane >> 4) * 4;
    int brow = lane & 7;
    int bcol = ((lane >> 3) & 1) * 4;
    int bhi  = (lane >> 4) * 8;

    // ---- stage Q into Ps, preload A-frags ----
    #pragma unroll
    for (int idx = tid; idx < 64 * 16; idx += 128) {
        int r = idx >> 4, c4 = (idx & 15) * 4;
        *(float4*)&Ps[r * AAP + c4] = *(const float4*)&Q[(size_t)(q0 + r) * HD + c4];
    }
    __syncthreads();

    uint32_t aq[8][4];
    #pragma unroll
    for (int ks = 0; ks < 8; ks++) {
        uint32_t addr = sPs + ((w * 16 + arow) * AAP + ks * 8 + acol) * 4;
        ldsm4(aq[ks][0], aq[ks][1], aq[ks][2], aq[ks][3], addr);
        cvt_tf32(aq[ks][0]); cvt_tf32(aq[ks][1]); cvt_tf32(aq[ks][2]); cvt_tf32(aq[ks][3]);
    }
    __syncthreads();

    float m_0 = -INFINITY, m_1 = -INFINITY, l_0 = 0.0f, l_1 = 0.0f;
    float o[8][4];
    #pragma unroll
    for (int nf = 0; nf < 8; nf++)
        #pragma unroll
        for (int r = 0; r < 4; r++) o[nf][r] = 0.0f;

    int vbr = tid >> 4;       // token block (0..7 via +8 loop)  [16 blocks total]
    int vbc = tid & 15;       // hd block

    for (int kt = 0; kt < L_ / 64; kt++) {
        int k0 = kt * 64;
        __syncthreads();      // previous tile fully consumed

        // K tile (64x64), direct
        #pragma unroll
        for (int idx = tid; idx < 64 * 16; idx += 128) {
            int r = idx >> 4, c4 = (idx & 15) * 4;
            *(float4*)&Ks[r * AAP + c4] = *(const float4*)&K[(size_t)(k0 + r) * HD + c4];
        }
        // V tile transposed: 16x16 blocks of 4x4, 2 blocks per thread
        #pragma unroll
        for (int i = 0; i < 2; i++) {
            int bl = tid + i * 128;
            int tb = bl >> 4;     // token block
            int hb = bl & 15;     // hd block
            float4 r0 = *(const float4*)&V[(size_t)(k0 + tb * 4 + 0) * HD + hb * 4];
            float4 r1 = *(const float4*)&V[(size_t)(k0 + tb * 4 + 1) * HD + hb * 4];
            float4 r2 = *(const float4*)&V[(size_t)(k0 + tb * 4 + 2) * HD + hb * 4];
            float4 r3 = *(const float4*)&V[(size_t)(k0 + tb * 4 + 3) * HD + hb * 4];
            *(float4*)&Vt[(hb * 4 + 0) * AAP + tb * 4] = make_float4(r0.x, r1.x, r2.x, r3.x);
            *(float4*)&Vt[(hb * 4 + 1) * AAP + tb * 4] = make_float4(r0.y, r1.y, r2.y, r3.y);
            *(float4*)&Vt[(hb * 4 + 2) * AAP + tb * 4] = make_float4(r0.z, r1.z, r2.z, r3.z);
            *(float4*)&Vt[(hb * 4 + 3) * AAP + tb * 4] = make_float4(r0.w, r1.w, r2.w, r3.w);
        }
        if (tid < 64) msk[tid] = maskw[b * L_ + k0 + tid];
        __syncthreads();

        // ---- S = Q @ K^T ----
        float sc[8][4];
        #pragma unroll
        for (int nf = 0; nf < 8; nf++)
            #pragma unroll
            for (int r = 0; r < 4; r++) sc[nf][r] = 0.0f;

        #pragma unroll
        for (int ks = 0; ks < 8; ks++) {
            int kc = ks * 8;
            uint32_t bfr[8][2];
            #pragma unroll
            for (int nf2 = 0; nf2 < 4; nf2++) {
                uint32_t addr = sKs + ((nf2 * 16 + bhi + brow) * AAP + kc + bcol) * 4;
                uint32_t r0, r1, r2, r3;
                ldsm4(r0, r1, r2, r3, addr);
                cvt_tf32(r0); cvt_tf32(r1); cvt_tf32(r2); cvt_tf32(r3);
                bfr[nf2 * 2][0] = r0; bfr[nf2 * 2][1] = r1;
                bfr[nf2 * 2 + 1][0] = r2; bfr[nf2 * 2 + 1][1] = r3;
            }
            #pragma unroll
            for (int nf = 0; nf < 8; nf++)
                mma_tf32(sc[nf], aq[ks], bfr[nf]);
        }

        // ---- online softmax (rows g, g+8 of warp tile) ----
        float mx0 = -INFINITY, mx1 = -INFINITY;
        #pragma unroll
        for (int nf = 0; nf < 8; nf++) {
            int c0 = nf * 8 + tq * 2;
            bool k0m = msk[c0] != 0;
            bool k1m = msk[c0 + 1] != 0;
            sc[nf][0] = k0m ? -1e8f : sc[nf][0] * SCALE_;
            sc[nf][1] = k1m ? -1e8f : sc[nf][1] * SCALE_;
            sc[nf][2] = k0m ? -1e8f : sc[nf][2] * SCALE_;
            sc[nf][3] = k1m ? -1e8f : sc[nf][3] * SCALE_;
            mx0 = fmaxf(mx0, fmaxf(sc[nf][0], sc[nf][1]));
            mx1 = fmaxf(mx1, fmaxf(sc[nf][2], sc[nf][3]));
        }
        mx0 = fmaxf(mx0, __shfl_xor_sync(0xffffffffu, mx0, 1));
        mx0 = fmaxf(mx0, __shfl_xor_sync(0xffffffffu, mx0, 2));
        mx1 = fmaxf(mx1, __shfl_xor_sync(0xffffffffu, mx1, 1));
        mx1 = fmaxf(mx1, __shfl_xor_sync(0xffffffffu, mx1, 2));

        float mn0 = fmaxf(m_0, mx0);
        float mn1 = fmaxf(m_1, mx1);
        float sc0 = __expf(m_0 - mn0);
        float sc1 = __expf(m_1 - mn1);

        float ll0 = 0.0f, ll1 = 0.0f;
        #pragma unroll
        for (int nf = 0; nf < 8; nf++) {
            float p0 = __expf(sc[nf][0] - mn0);
            float p1 = __expf(sc[nf][1] - mn0);
            float p2 = __expf(sc[nf][2] - mn1);
            float p3 = __expf(sc[nf][3] - mn1);
            ll0 += p0 + p1;
            ll1 += p2 + p3;
            int c0 = nf * 8 + tq * 2;
            *(float2*)&Ps[(w * 16 + g) * AAP + c0]     = make_float2(p0, p1);
            *(float2*)&Ps[(w * 16 + g + 8) * AAP + c0] = make_float2(p2, p3);
        }
        ll0 += __shfl_xor_sync(0xffffffffu, ll0, 1);
        ll0 += __shfl_xor_sync(0xffffffffu, ll0, 2);
        ll1 += __shfl_xor_sync(0xffffffffu, ll1, 1);
        ll1 += __shfl_xor_sync(0xffffffffu, ll1, 2);

        l_0 = l_0 * sc0 + ll0;
        l_1 = l_1 * sc1 + ll1;
        m_0 = mn0;
        m_1 = mn1;

        #pragma unroll
        for (int nf = 0; nf < 8; nf++) {
            o[nf][0] *= sc0; o[nf][1] *= sc0;
            o[nf][2] *= sc1; o[nf][3] *= sc1;
        }
        __syncwarp();     // Ps rows are warp-private

        // ---- O += P @ V ----
        #pragma unroll
        for (int ks = 0; ks < 8; ks++) {
            int kc = ks * 8;
            uint32_t ap[4];
            {
                uint32_t addr = sPs + ((w * 16 + arow) * AAP + kc + acol) * 4;
                ldsm4(ap[0], ap[1], ap[2], ap[3], addr);
                cvt_tf32(ap[0]); cvt_tf32(ap[1]); cvt_tf32(ap[2]); cvt_tf32(ap[3]);
            }
            uint32_t bfr[8][2];
            #pragma unroll
            for (int nf2 = 0; nf2 < 4; nf2++) {
                uint32_t addr = sVt + ((nf2 * 16 + bhi + brow) * AAP + kc + bcol) * 4;
                uint32_t r0, r1, r2, r3;
                ldsm4(r0, r1, r2, r3, addr);
                cvt_tf32(r0); cvt_tf32(r1); cvt_tf32(r2); cvt_tf32(r3);
                bfr[nf2 * 2][0] = r0; bfr[nf2 * 2][1] = r1;
                bfr[nf2 * 2 + 1][0] = r2; bfr[nf2 * 2 + 1][1] = r3;
            }
            #pragma unroll
            for (int nf = 0; nf < 8; nf++)
                mma_tf32(o[nf], ap, bfr[nf]);
        }
    }

    // ---- epilogue: normalize & store ----
    float inv0 = 1.0f / l_0;
    float inv1 = 1.0f / l_1;
    int r0g = q0 + w * 16 + g;
    int r1g = r0g + 8;
    #pragma unroll
    for (int nf = 0; nf < 8; nf++) {
        int col = n * HD + nf * 8 + tq * 2;
        *(float2*)&g_Ctx[((size_t)(b * L_ + r0g)) * D_ + col] =
            make_float2(o[nf][0] * inv0, o[nf][1] * inv0);
        *(float2*)&g_Ctx[((size_t)(b * L_ + r1g)) * D_ + col] =
            make_float2(o[nf][2] * inv1, o[nf][3] * inv1);
    }
}

// ---------------------------------------------------------------------------
// Inputs: 0=q 1=k 2=v 3=mask 4=Wq 5=bq 6=Wk 7=bk 8=Wv 9=bv 10=Wo 11=bo
// ---------------------------------------------------------------------------
extern "C" void kernel_launch(void* const* d_in, const int* in_sizes, int n_in,
                              void* d_out, int out_size) {
    const float* q  = (const float*)d_in[0];
    const float* k  = (const float*)d_in[1];
    const float* v  = (const float*)d_in[2];
    const unsigned int* mask = (const unsigned int*)d_in[3];
    const float* Wq = (const float*)d_in[4];
    const float* bq = (const float*)d_in[5];
    const float* Wk = (const float*)d_in[6];
    const float* bk = (const float*)d_in[7];
    const float* Wv = (const float*)d_in[8];
    const float* bv = (const float*)d_in[9];
    const float* Wo = (const float*)d_in[10];
    const float* bo = (const float*)d_in[11];
    float* out = (float*)d_out;

    cudaFuncSetAttribute(attn_mma_kernel, cudaFuncAttributeMaxDynamicSharedMemorySize, ATT_SMEM);
    cudaFuncSetAttribute(mma_qkv_kernel, cudaFuncAttributeMaxDynamicSharedMemorySize, GEMM_SMEM);
    cudaFuncSetAttribute(mma_out_kernel, cudaFuncAttributeMaxDynamicSharedMemorySize, GEMM_SMEM);

    rope_table_kernel<<<(L_ * (HD / 2) + 255) / 256, 256>>>();
    mma_qkv_kernel<<<dim3(D_ / 128, M_ / 128, 3), 256, GEMM_SMEM>>>(
        q, k, v, Wq, bq, Wk, bk, Wv, bv);
    attn_mma_kernel<<<dim3(L_ / 64, B_ * NH), 128, ATT_SMEM>>>(mask);
    mma_out_kernel<<<dim3(D_ / 128, M_ / 128), 256, GEMM_SMEM>>>(Wo, bo, out);
}